// round 7
// baseline (speedup 1.0000x reference)
#include <cuda_runtime.h>
#include <cuda_bf16.h>
#include <cstdint>

#define NB   8
#define TGT  256
#define SRC  512
#define DIM  1024
#define NH   16
#define DH   64

typedef unsigned int u32;
typedef unsigned long long u64;

// ---------------- device scratch (no cudaMalloc allowed) --------------------
__device__ __nv_bfloat16 g_seq_hi[(size_t)NB * TGT * DIM];
__device__ __nv_bfloat16 g_seq_lo[(size_t)NB * TGT * DIM];
__device__ __nv_bfloat16 g_key_hi[(size_t)NB * SRC * DIM];
__device__ __nv_bfloat16 g_key_lo[(size_t)NB * SRC * DIM];
__device__ __nv_bfloat16 g_qw_hi[(size_t)DIM * DIM];
__device__ __nv_bfloat16 g_qw_lo[(size_t)DIM * DIM];
__device__ __nv_bfloat16 g_kw_hi[(size_t)DIM * DIM];
__device__ __nv_bfloat16 g_kw_lo[(size_t)DIM * DIM];
__device__ __nv_bfloat16 g_q_hi[(size_t)NB * TGT * DIM];
__device__ __nv_bfloat16 g_q_lo[(size_t)NB * TGT * DIM];
__device__ __nv_bfloat16 g_k_hi[(size_t)NB * SRC * DIM];
__device__ __nv_bfloat16 g_k_lo[(size_t)NB * SRC * DIM];

// ---------------- PTX helpers -----------------------------------------------
__device__ __forceinline__ u32 smem_u32(const void* p) {
    u32 a;
    asm("{ .reg .u64 t; cvta.to.shared.u64 t, %1; cvt.u32.u64 %0, t; }"
        : "=r"(a) : "l"(p));
    return a;
}

__device__ __forceinline__ u32 swz(u32 off) { return off ^ ((off >> 3) & 0x70); }

#define CP_ASYNC16(dst, src) \
    asm volatile("cp.async.cg.shared.global [%0], [%1], 16;" \
                 :: "r"(dst), "l"(src) : "memory")
#define CP_COMMIT() asm volatile("cp.async.commit_group;" ::: "memory")
#define CP_WAIT(n)  asm volatile("cp.async.wait_group %0;" :: "n"(n) : "memory")

__device__ __forceinline__ void ldsm4(u32& r0, u32& r1, u32& r2, u32& r3, u32 addr) {
    asm volatile("ldmatrix.sync.aligned.m8n8.x4.shared.b16 {%0,%1,%2,%3}, [%4];"
                 : "=r"(r0), "=r"(r1), "=r"(r2), "=r"(r3) : "r"(addr));
}

__device__ __forceinline__ void mma16816(float* c, const u32* a, const u32* b) {
    asm volatile(
        "mma.sync.aligned.m16n8k16.row.col.f32.bf16.bf16.f32 "
        "{%0,%1,%2,%3}, {%4,%5,%6,%7}, {%8,%9}, {%0,%1,%2,%3};"
        : "+f"(c[0]), "+f"(c[1]), "+f"(c[2]), "+f"(c[3])
        : "r"(a[0]), "r"(a[1]), "r"(a[2]), "r"(a[3]), "r"(b[0]), "r"(b[1]));
}

// ---------------------------------------------------------------------------
// Fused fp32 -> (hi, lo) bf16 split for all four inputs in ONE launch.
// ---------------------------------------------------------------------------
#define N4_SEQ  (NB * TGT * DIM / 4)
#define N4_KEY  (NB * SRC * DIM / 4)
#define N4_W    (DIM * DIM / 4)
#define N4_TOT  (N4_SEQ + N4_KEY + 2 * N4_W)

__global__ __launch_bounds__(256) void split_all_kernel(
    const float* __restrict__ seqs, const float* __restrict__ keys,
    const float* __restrict__ qw, const float* __restrict__ kw) {
    int i = blockIdx.x * 256 + threadIdx.x;
    if (i >= N4_TOT) return;
    const float* src;
    __nv_bfloat16 *hi, *lo;
    int j = i;
    if (j < N4_SEQ) {
        src = seqs; hi = g_seq_hi; lo = g_seq_lo;
    } else if ((j -= N4_SEQ) < N4_KEY) {
        src = keys; hi = g_key_hi; lo = g_key_lo;
    } else if ((j -= N4_KEY) < N4_W) {
        src = qw; hi = g_qw_hi; lo = g_qw_lo;
    } else {
        j -= N4_W;
        src = kw; hi = g_kw_hi; lo = g_kw_lo;
    }
    float4 v = ((const float4*)src)[j];
    __nv_bfloat16 h[4], l[4];
    h[0] = __float2bfloat16(v.x); l[0] = __float2bfloat16(v.x - __bfloat162float(h[0]));
    h[1] = __float2bfloat16(v.y); l[1] = __float2bfloat16(v.y - __bfloat162float(h[1]));
    h[2] = __float2bfloat16(v.z); l[2] = __float2bfloat16(v.z - __bfloat162float(h[2]));
    h[3] = __float2bfloat16(v.w); l[3] = __float2bfloat16(v.w - __bfloat162float(h[3]));
    ((uint2*)hi)[j] = *(uint2*)h;
    ((uint2*)lo)[j] = *(uint2*)l;
}

// ---------------------------------------------------------------------------
// Combined projection: both q and k projections in ONE launch.
// ---------------------------------------------------------------------------
#define PROJ_SMEM (1024 + 2 * 32768)

__global__ __launch_bounds__(256, 2) void proj_kernel(
    const float* __restrict__ q_b, const float* __restrict__ k_b) {
    extern __shared__ char smraw[];
    u32 braw = smem_u32(smraw);
    u32 base = (braw + 1023) & ~1023u;

    const int tid = threadIdx.x, lane = tid & 31, wid = tid >> 5;
    const bool isQ = blockIdx.x < 16;
    const int m0 = (isQ ? blockIdx.x : (blockIdx.x - 16)) * 128;
    const int n0 = blockIdx.y * 128;

    const __nv_bfloat16* Ahi = isQ ? g_seq_hi : g_key_hi;
    const __nv_bfloat16* Alo = isQ ? g_seq_lo : g_key_lo;
    const __nv_bfloat16* Whi = isQ ? g_qw_hi : g_kw_hi;
    const __nv_bfloat16* Wlo = isQ ? g_qw_lo : g_kw_lo;
    const float* bias = isQ ? q_b : k_b;
    __nv_bfloat16* Chi = isQ ? g_q_hi : g_k_hi;
    __nv_bfloat16* Clo = isQ ? g_q_lo : g_k_lo;

    const int wm0 = (wid >> 1) * 32, wn0 = (wid & 1) * 64;

    const __nv_bfloat16* segA[3] = {Ahi, Ahi, Alo};
    const __nv_bfloat16* segB[3] = {Whi, Wlo, Whi};

    const int r0l = tid >> 3, grp = tid & 7;

    auto load_chunk = [&](int c, int st) {
        int seg = c >> 4;
        int k0 = (c & 15) * 64;
        const __nv_bfloat16* As = segA[seg];
        const __nv_bfloat16* Bs = segB[seg];
        u32 Ab = base + (u32)st * 32768u;
        u32 Bb = Ab + 16384u;
#pragma unroll
        for (int g = 0; g < 4; g++) {
            int row = r0l + g * 32;
            u32 d = swz((u32)(row * 128 + grp * 16));
            CP_ASYNC16(Ab + d, As + (size_t)(m0 + row) * DIM + k0 + grp * 8);
            CP_ASYNC16(Bb + d, Bs + (size_t)(n0 + row) * DIM + k0 + grp * 8);
        }
        CP_COMMIT();
    };

    load_chunk(0, 0);
    load_chunk(1, 1);

    float acc[2][8][4];
#pragma unroll
    for (int i = 0; i < 2; i++)
#pragma unroll
        for (int j = 0; j < 8; j++)
#pragma unroll
            for (int q = 0; q < 4; q++) acc[i][j][q] = 0.f;

    const int lrA = wm0 + (lane & 15);
    const int lrB = wn0 + (lane & 15);
    const u32 khi = (u32)((lane >> 4) << 4);

    for (int c = 0; c < 48; c++) {
        const int st = c & 1;
        CP_WAIT(1);
        __syncthreads();
        u32 Ab = base + (u32)st * 32768u;
        u32 Bb = Ab + 16384u;
#pragma unroll
        for (int kk = 0; kk < 4; kk++) {
            u32 kb = (u32)(kk * 32) + khi;
            u32 a0[4], a1[4];
            ldsm4(a0[0], a0[1], a0[2], a0[3], Ab + swz((u32)(lrA * 128) + kb));
            ldsm4(a1[0], a1[1], a1[2], a1[3], Ab + swz((u32)((lrA + 16) * 128) + kb));
            u32 b[8][2];
#pragma unroll
            for (int nn = 0; nn < 4; nn++) {
                u32 t0, t1, t2, t3;
                ldsm4(t0, t1, t2, t3, Bb + swz((u32)((lrB + nn * 16) * 128) + kb));
                b[2 * nn][0] = t0; b[2 * nn + 1][0] = t1;
                b[2 * nn][1] = t2; b[2 * nn + 1][1] = t3;
            }
#pragma unroll
            for (int ni = 0; ni < 8; ni++) {
                mma16816(acc[0][ni], a0, b[ni]);
                mma16816(acc[1][ni], a1, b[ni]);
            }
        }
        __syncthreads();
        if (c + 2 < 48) load_chunk(c + 2, st);
    }

    const int g = lane >> 2, tg = lane & 3;
#pragma unroll
    for (int ni = 0; ni < 8; ni++) {
        int n = n0 + wn0 + ni * 8 + 2 * tg;
        float b0 = bias[n], b1 = bias[n + 1];
#pragma unroll
        for (int mi = 0; mi < 2; mi++) {
#pragma unroll
            for (int half = 0; half < 2; half++) {
                int m = m0 + wm0 + mi * 16 + half * 8 + g;
                float v0 = fmaxf(acc[mi][ni][half * 2 + 0] + b0, 0.f);
                float v1 = fmaxf(acc[mi][ni][half * 2 + 1] + b1, 0.f);
                __nv_bfloat16 h0 = __float2bfloat16(v0);
                __nv_bfloat16 h1 = __float2bfloat16(v1);
                __nv_bfloat16 l0 = __float2bfloat16(v0 - __bfloat162float(h0));
                __nv_bfloat16 l1 = __float2bfloat16(v1 - __bfloat162float(h1));
                __nv_bfloat162 hp; hp.x = h0; hp.y = h1;
                __nv_bfloat162 lp; lp.x = l0; lp.y = l1;
                *(__nv_bfloat162*)(Chi + (size_t)m * DIM + n) = hp;
                *(__nv_bfloat162*)(Clo + (size_t)m * DIM + n) = lp;
            }
        }
    }
}

// ---------------------------------------------------------------------------
// Energy: p[bh,t,s] = sigmoid(5*(q.k*0.125 + eb)), split-bf16 HMMA.
// ---------------------------------------------------------------------------
#define EN_SMEM (1024 + 3 * 32768)

__device__ __forceinline__ float sigmoid5(float e) {
    return 1.f / (1.f + __expf(-5.f * e));
}

__global__ __launch_bounds__(256, 2) void energy_kernel(
    const float* __restrict__ ebias, float* __restrict__ p) {
    extern __shared__ char smraw[];
    u32 braw = smem_u32(smraw);
    u32 base = (braw + 1023) & ~1023u;

    const int tid = threadIdx.x, lane = tid & 31, wid = tid >> 5;
    const int s0 = blockIdx.x * 128, t0 = blockIdx.y * 128;
    const int bh = blockIdx.z;
    const int b = bh >> 4, h = bh & 15;
    const int wm0 = (wid >> 1) * 32, wn0 = (wid & 1) * 64;

    const __nv_bfloat16* segQ[3] = {g_q_hi, g_q_hi, g_q_lo};
    const __nv_bfloat16* segK[3] = {g_k_hi, g_k_lo, g_k_hi};

    const int r0l = tid >> 3, grp = tid & 7;

#pragma unroll
    for (int c = 0; c < 3; c++) {
        const __nv_bfloat16* Qs = segQ[c];
        const __nv_bfloat16* Ks = segK[c];
        u32 Qb = base + (u32)c * 32768u;
        u32 Kb = Qb + 16384u;
#pragma unroll
        for (int g = 0; g < 4; g++) {
            int row = r0l + g * 32;
            u32 d = swz((u32)(row * 128 + grp * 16));
            CP_ASYNC16(Qb + d, Qs + (size_t)(b * TGT + t0 + row) * DIM + h * DH + grp * 8);
            CP_ASYNC16(Kb + d, Ks + (size_t)(b * SRC + s0 + row) * DIM + h * DH + grp * 8);
        }
        CP_COMMIT();
    }
    CP_WAIT(0);
    __syncthreads();

    float acc[2][8][4];
#pragma unroll
    for (int i = 0; i < 2; i++)
#pragma unroll
        for (int j = 0; j < 8; j++)
#pragma unroll
            for (int q = 0; q < 4; q++) acc[i][j][q] = 0.f;

    const int lrA = wm0 + (lane & 15);
    const int lrB = wn0 + (lane & 15);
    const u32 khi_off = (u32)((lane >> 4) << 4);

#pragma unroll
    for (int c = 0; c < 3; c++) {
        u32 Qb = base + (u32)c * 32768u;
        u32 Kb = Qb + 16384u;
#pragma unroll
        for (int kk = 0; kk < 4; kk++) {
            u32 kb = (u32)(kk * 32) + khi_off;
            u32 a0[4], a1[4];
            ldsm4(a0[0], a0[1], a0[2], a0[3], Qb + swz((u32)(lrA * 128) + kb));
            ldsm4(a1[0], a1[1], a1[2], a1[3], Qb + swz((u32)((lrA + 16) * 128) + kb));
            u32 bb[8][2];
#pragma unroll
            for (int nn = 0; nn < 4; nn++) {
                u32 t0r, t1r, t2r, t3r;
                ldsm4(t0r, t1r, t2r, t3r, Kb + swz((u32)((lrB + nn * 16) * 128) + kb));
                bb[2 * nn][0] = t0r; bb[2 * nn + 1][0] = t1r;
                bb[2 * nn][1] = t2r; bb[2 * nn + 1][1] = t3r;
            }
#pragma unroll
            for (int ni = 0; ni < 8; ni++) {
                mma16816(acc[0][ni], a0, bb[ni]);
                mma16816(acc[1][ni], a1, bb[ni]);
            }
        }
    }

    const float eb = ebias[0];
    const int g = lane >> 2, tg = lane & 3;
#pragma unroll
    for (int ni = 0; ni < 8; ni++) {
        int s = s0 + wn0 + ni * 8 + 2 * tg;
#pragma unroll
        for (int mi = 0; mi < 2; mi++) {
#pragma unroll
            for (int half = 0; half < 2; half++) {
                int t = t0 + wm0 + mi * 16 + half * 8 + g;
                float2 o;
                o.x = sigmoid5(acc[mi][ni][half * 2 + 0] * 0.125f + eb);
                o.y = sigmoid5(acc[mi][ni][half * 2 + 1] * 0.125f + eb);
                *(float2*)(p + ((size_t)bh * TGT + t) * SRC + s) = o;
            }
        }
    }
}

// ---------------------------------------------------------------------------
// Monotonic alignment: one warp per TWO bh rows, interleaved for ILP.
// Per row, per 2 t-steps: local 2x8 chains (ILP), warp scan of 2x2 affine
// maps, seed-recompute. The two rows' chains/shuffles/loads are independent,
// filling each other's stall slots.
// ---------------------------------------------------------------------------
__global__ __launch_bounds__(32) void align_kernel(
    const float* __restrict__ p, float* __restrict__ alpha) {
    const int lane = threadIdx.x;
    const float* prow[2];
    float* arow[2];
#pragma unroll
    for (int r = 0; r < 2; r++) {
        int bh = blockIdx.x * 2 + r;
        prow[r] = p + (size_t)bh * TGT * SRC + lane * 16;
        arow[r] = alpha + (size_t)bh * TGT * SRC + lane * 16;
    }

    float b[2][16];
#pragma unroll
    for (int r = 0; r < 2; r++) {
#pragma unroll
        for (int i = 0; i < 16; i++) b[r][i] = 0.f;
        if (lane == 0) b[r][0] = 1.f;
    }

    float4 f[2][8];
#pragma unroll
    for (int r = 0; r < 2; r++)
#pragma unroll
        for (int j = 0; j < 4; j++) {
            f[r][j]     = *(const float4*)(prow[r] + 0 * SRC + 4 * j);
            f[r][4 + j] = *(const float4*)(prow[r] + 1 * SRC + 4 * j);
        }

    for (int tp = 0; tp < TGT / 2; tp++) {
        float pt[2][16], pt1[2][16];
#pragma unroll
        for (int r = 0; r < 2; r++)
#pragma unroll
            for (int j = 0; j < 4; j++) {
                pt[r][4 * j + 0] = f[r][j].x;  pt[r][4 * j + 1] = f[r][j].y;
                pt[r][4 * j + 2] = f[r][j].z;  pt[r][4 * j + 3] = f[r][j].w;
                pt1[r][4 * j + 0] = f[r][4 + j].x; pt1[r][4 * j + 1] = f[r][4 + j].y;
                pt1[r][4 * j + 2] = f[r][4 + j].z; pt1[r][4 * j + 3] = f[r][4 + j].w;
            }
        if (tp + 1 < TGT / 2) {
#pragma unroll
            for (int r = 0; r < 2; r++) {
                const float* np = prow[r] + (size_t)(2 * tp + 2) * SRC;
#pragma unroll
                for (int j = 0; j < 4; j++) {
                    f[r][j]     = *(const float4*)(np + 4 * j);
                    f[r][4 + j] = *(const float4*)(np + SRC + 4 * j);
                }
            }
        }

        float atf[2], at1f[2];
#pragma unroll
        for (int r = 0; r < 2; r++) {
            float ptm  = __shfl_up_sync(0xffffffffu, pt[r][15], 1);
            float pt1m = __shfl_up_sync(0xffffffffu, pt1[r][15], 1);
            atf[r]  = lane ? (1.f - ptm)  : 0.f;
            at1f[r] = lane ? (1.f - pt1m) : 0.f;
        }

        // local chains: 2 halves x 2 rows, 4 independent chain groups
        float C00[2][2], C10[2][2], C11[2][2], LXa[2][2], LYa[2][2];
#pragma unroll
        for (int h = 0; h < 2; h++) {
            float c00[2], c10[2], c11[2], x[2], y[2];
#pragma unroll
            for (int r = 0; r < 2; r++) { c00[r] = 1.f; c10[r] = 0.f; c11[r] = 1.f; x[r] = 0.f; y[r] = 0.f; }
#pragma unroll
            for (int i = 0; i < 8; i++) {
#pragma unroll
                for (int r = 0; r < 2; r++) {
                    int e = h * 8 + i;
                    float at  = (e == 0) ? atf[r]  : (1.f - pt[r][e - 1]);
                    float at1 = (e == 0) ? at1f[r] : (1.f - pt1[r][e - 1]);
                    x[r] = fmaf(at, x[r], b[r][e]);
                    y[r] = fmaf(at1, y[r], pt[r][e] * x[r]);
                    c00[r] = at * c00[r];
                    c10[r] = fmaf(pt[r][e], c00[r], at1 * c10[r]);
                    c11[r] = at1 * c11[r];
                }
            }
#pragma unroll
            for (int r = 0; r < 2; r++) {
                C00[h][r] = c00[r]; C10[h][r] = c10[r]; C11[h][r] = c11[r];
                LXa[h][r] = x[r]; LYa[h][r] = y[r];
            }
        }

        // lane totals (per row)
        float s00[2], s10[2], s11[2], X[2], Y[2];
#pragma unroll
        for (int r = 0; r < 2; r++) {
            s00[r] = C00[1][r] * C00[0][r];
            s10[r] = fmaf(C10[1][r], C00[0][r], C11[1][r] * C10[0][r]);
            s11[r] = C11[1][r] * C11[0][r];
            X[r]   = fmaf(C00[1][r], LXa[0][r], LXa[1][r]);
            Y[r]   = fmaf(C10[1][r], LXa[0][r], fmaf(C11[1][r], LYa[0][r], LYa[1][r]));
        }

        // warp inclusive scan (both rows interleaved, 10 shuffles/round)
#pragma unroll
        for (int d = 1; d < 32; d <<= 1) {
            bool use = (lane >= d);
#pragma unroll
            for (int r = 0; r < 2; r++) {
                float g00 = __shfl_up_sync(0xffffffffu, s00[r], d);
                float g10 = __shfl_up_sync(0xffffffffu, s10[r], d);
                float g11 = __shfl_up_sync(0xffffffffu, s11[r], d);
                float gX  = __shfl_up_sync(0xffffffffu, X[r], d);
                float gY  = __shfl_up_sync(0xffffffffu, Y[r], d);
                float nX  = fmaf(s00[r], gX, X[r]);
                float nY  = fmaf(s10[r], gX, fmaf(s11[r], gY, Y[r]));
                float n00 = s00[r] * g00;
                float n10 = fmaf(s10[r], g00, s11[r] * g10);
                float n11 = s11[r] * g11;
                X[r] = use ? nX : X[r];     Y[r] = use ? nY : Y[r];
                s00[r] = use ? n00 : s00[r]; s10[r] = use ? n10 : s10[r];
                s11[r] = use ? n11 : s11[r];
            }
        }

        float Xin[2], Yin[2];
#pragma unroll
        for (int r = 0; r < 2; r++) {
            float xi = __shfl_up_sync(0xffffffffu, X[r], 1);
            float yi = __shfl_up_sync(0xffffffffu, Y[r], 1);
            Xin[r] = lane ? xi : 0.f;
            Yin[r] = lane ? yi : 0.f;
        }

        // half seeds + seed-recompute (4 independent chains) + outputs
        float SX[2][2], SY[2][2];
#pragma unroll
        for (int r = 0; r < 2; r++) {
            SX[0][r] = Xin[r];
            SY[0][r] = Yin[r];
            SX[1][r] = fmaf(C00[0][r], Xin[r], LXa[0][r]);
            SY[1][r] = fmaf(C10[0][r], Xin[r], fmaf(C11[0][r], Yin[r], LYa[0][r]));
        }

        float ot[2][16];
#pragma unroll
        for (int h = 0; h < 2; h++) {
            float x[2], y[2];
#pragma unroll
            for (int r = 0; r < 2; r++) { x[r] = SX[h][r]; y[r] = SY[h][r]; }
#pragma unroll
            for (int i = 0; i < 8; i++) {
#pragma unroll
                for (int r = 0; r < 2; r++) {
                    int e = h * 8 + i;
                    float at  = (e == 0) ? atf[r]  : (1.f - pt[r][e - 1]);
                    float at1 = (e == 0) ? at1f[r] : (1.f - pt1[r][e - 1]);
                    x[r] = fmaf(at, x[r], b[r][e]);
                    float o = pt[r][e] * x[r];
                    y[r] = fmaf(at1, y[r], o);
                    ot[r][e] = o;
                    b[r][e] = pt1[r][e] * y[r];
                }
            }
        }
#pragma unroll
        for (int r = 0; r < 2; r++) {
            float* a0 = arow[r] + (size_t)(2 * tp) * SRC;
            float* a1 = a0 + SRC;
#pragma unroll
            for (int j = 0; j < 4; j++) {
                *(float4*)(a0 + 4 * j) = make_float4(ot[r][4 * j], ot[r][4 * j + 1],
                                                     ot[r][4 * j + 2], ot[r][4 * j + 3]);
                *(float4*)(a1 + 4 * j) = make_float4(b[r][4 * j], b[r][4 * j + 1],
                                                     b[r][4 * j + 2], b[r][4 * j + 3]);
            }
        }
    }
}

// ---------------------------------------------------------------------------
extern "C" void kernel_launch(void* const* d_in, const int* in_sizes, int n_in,
                              void* d_out, int out_size) {
    const float* seqs = (const float*)d_in[0];
    const float* keys = (const float*)d_in[1];
    const float* q_w  = (const float*)d_in[2];
    const float* q_b  = (const float*)d_in[3];
    const float* k_w  = (const float*)d_in[4];
    const float* k_b  = (const float*)d_in[5];
    const float* eb   = (const float*)d_in[6];

    float* out   = (float*)d_out;
    float* p     = out;
    float* alpha = out + (size_t)NB * NH * TGT * SRC;

    cudaFuncSetAttribute(proj_kernel, cudaFuncAttributeMaxDynamicSharedMemorySize, PROJ_SMEM);
    cudaFuncSetAttribute(energy_kernel, cudaFuncAttributeMaxDynamicSharedMemorySize, EN_SMEM);

    // fused fp32 -> bf16 hi/lo splits (one launch)
    split_all_kernel<<<(N4_TOT + 255) / 256, 256>>>(seqs, keys, q_w, k_w);

    // both projections in one launch (x: 16 q-tiles + 32 k-tiles)
    proj_kernel<<<dim3(48, DIM / 128), 256, PROJ_SMEM>>>(q_b, k_b);

    // p_choose (HMMA)
    energy_kernel<<<dim3(SRC / 128, TGT / 128, NB * NH), 256, EN_SMEM>>>(eb, p);

    // alpha: 64 warps, 2 bh rows per warp (interleaved)
    align_kernel<<<NB * NH / 2, 32>>>(p, alpha);
}

// round 8
// speedup vs baseline: 1.0206x; 1.0206x over previous
#include <cuda_runtime.h>
#include <cuda_bf16.h>
#include <cstdint>

#define NB   8
#define TGT  256
#define SRC  512
#define DIM  1024
#define NH   16
#define DH   64

typedef unsigned int u32;
typedef unsigned long long u64;

// ---------------- device scratch (no cudaMalloc allowed) --------------------
__device__ __nv_bfloat16 g_seq_hi[(size_t)NB * TGT * DIM];
__device__ __nv_bfloat16 g_seq_lo[(size_t)NB * TGT * DIM];
__device__ __nv_bfloat16 g_key_hi[(size_t)NB * SRC * DIM];
__device__ __nv_bfloat16 g_key_lo[(size_t)NB * SRC * DIM];
__device__ __nv_bfloat16 g_qw_hi[(size_t)DIM * DIM];
__device__ __nv_bfloat16 g_qw_lo[(size_t)DIM * DIM];
__device__ __nv_bfloat16 g_kw_hi[(size_t)DIM * DIM];
__device__ __nv_bfloat16 g_kw_lo[(size_t)DIM * DIM];
__device__ __nv_bfloat16 g_q_hi[(size_t)NB * TGT * DIM];
__device__ __nv_bfloat16 g_q_lo[(size_t)NB * TGT * DIM];
__device__ __nv_bfloat16 g_k_hi[(size_t)NB * SRC * DIM];
__device__ __nv_bfloat16 g_k_lo[(size_t)NB * SRC * DIM];

// ---------------- PTX helpers -----------------------------------------------
__device__ __forceinline__ u32 smem_u32(const void* p) {
    u32 a;
    asm("{ .reg .u64 t; cvta.to.shared.u64 t, %1; cvt.u32.u64 %0, t; }"
        : "=r"(a) : "l"(p));
    return a;
}

__device__ __forceinline__ u32 swz(u32 off) { return off ^ ((off >> 3) & 0x70); }

#define CP_ASYNC16(dst, src) \
    asm volatile("cp.async.cg.shared.global [%0], [%1], 16;" \
                 :: "r"(dst), "l"(src) : "memory")
#define CP_COMMIT() asm volatile("cp.async.commit_group;" ::: "memory")
#define CP_WAIT(n)  asm volatile("cp.async.wait_group %0;" :: "n"(n) : "memory")

__device__ __forceinline__ void ldsm4(u32& r0, u32& r1, u32& r2, u32& r3, u32 addr) {
    asm volatile("ldmatrix.sync.aligned.m8n8.x4.shared.b16 {%0,%1,%2,%3}, [%4];"
                 : "=r"(r0), "=r"(r1), "=r"(r2), "=r"(r3) : "r"(addr));
}

__device__ __forceinline__ void mma16816(float* c, const u32* a, const u32* b) {
    asm volatile(
        "mma.sync.aligned.m16n8k16.row.col.f32.bf16.bf16.f32 "
        "{%0,%1,%2,%3}, {%4,%5,%6,%7}, {%8,%9}, {%0,%1,%2,%3};"
        : "+f"(c[0]), "+f"(c[1]), "+f"(c[2]), "+f"(c[3])
        : "r"(a[0]), "r"(a[1]), "r"(a[2]), "r"(a[3]), "r"(b[0]), "r"(b[1]));
}

// ---------------------------------------------------------------------------
// Fused fp32 -> (hi, lo) bf16 split for all four inputs in ONE launch.
// ---------------------------------------------------------------------------
#define N4_SEQ  (NB * TGT * DIM / 4)
#define N4_KEY  (NB * SRC * DIM / 4)
#define N4_W    (DIM * DIM / 4)
#define N4_TOT  (N4_SEQ + N4_KEY + 2 * N4_W)

__global__ __launch_bounds__(256) void split_all_kernel(
    const float* __restrict__ seqs, const float* __restrict__ keys,
    const float* __restrict__ qw, const float* __restrict__ kw) {
    int i = blockIdx.x * 256 + threadIdx.x;
    if (i >= N4_TOT) return;
    const float* src;
    __nv_bfloat16 *hi, *lo;
    int j = i;
    if (j < N4_SEQ) {
        src = seqs; hi = g_seq_hi; lo = g_seq_lo;
    } else if ((j -= N4_SEQ) < N4_KEY) {
        src = keys; hi = g_key_hi; lo = g_key_lo;
    } else if ((j -= N4_KEY) < N4_W) {
        src = qw; hi = g_qw_hi; lo = g_qw_lo;
    } else {
        j -= N4_W;
        src = kw; hi = g_kw_hi; lo = g_kw_lo;
    }
    float4 v = ((const float4*)src)[j];
    __nv_bfloat16 h[4], l[4];
    h[0] = __float2bfloat16(v.x); l[0] = __float2bfloat16(v.x - __bfloat162float(h[0]));
    h[1] = __float2bfloat16(v.y); l[1] = __float2bfloat16(v.y - __bfloat162float(h[1]));
    h[2] = __float2bfloat16(v.z); l[2] = __float2bfloat16(v.z - __bfloat162float(h[2]));
    h[3] = __float2bfloat16(v.w); l[3] = __float2bfloat16(v.w - __bfloat162float(h[3]));
    ((uint2*)hi)[j] = *(uint2*)h;
    ((uint2*)lo)[j] = *(uint2*)l;
}

// ---------------------------------------------------------------------------
// Combined projection: both q and k projections in ONE launch.
// ---------------------------------------------------------------------------
#define PROJ_SMEM (1024 + 2 * 32768)

__global__ __launch_bounds__(256, 2) void proj_kernel(
    const float* __restrict__ q_b, const float* __restrict__ k_b) {
    extern __shared__ char smraw[];
    u32 braw = smem_u32(smraw);
    u32 base = (braw + 1023) & ~1023u;

    const int tid = threadIdx.x, lane = tid & 31, wid = tid >> 5;
    const bool isQ = blockIdx.x < 16;
    const int m0 = (isQ ? blockIdx.x : (blockIdx.x - 16)) * 128;
    const int n0 = blockIdx.y * 128;

    const __nv_bfloat16* Ahi = isQ ? g_seq_hi : g_key_hi;
    const __nv_bfloat16* Alo = isQ ? g_seq_lo : g_key_lo;
    const __nv_bfloat16* Whi = isQ ? g_qw_hi : g_kw_hi;
    const __nv_bfloat16* Wlo = isQ ? g_qw_lo : g_kw_lo;
    const float* bias = isQ ? q_b : k_b;
    __nv_bfloat16* Chi = isQ ? g_q_hi : g_k_hi;
    __nv_bfloat16* Clo = isQ ? g_q_lo : g_k_lo;

    const int wm0 = (wid >> 1) * 32, wn0 = (wid & 1) * 64;

    const __nv_bfloat16* segA[3] = {Ahi, Ahi, Alo};
    const __nv_bfloat16* segB[3] = {Whi, Wlo, Whi};

    const int r0l = tid >> 3, grp = tid & 7;

    auto load_chunk = [&](int c, int st) {
        int seg = c >> 4;
        int k0 = (c & 15) * 64;
        const __nv_bfloat16* As = segA[seg];
        const __nv_bfloat16* Bs = segB[seg];
        u32 Ab = base + (u32)st * 32768u;
        u32 Bb = Ab + 16384u;
#pragma unroll
        for (int g = 0; g < 4; g++) {
            int row = r0l + g * 32;
            u32 d = swz((u32)(row * 128 + grp * 16));
            CP_ASYNC16(Ab + d, As + (size_t)(m0 + row) * DIM + k0 + grp * 8);
            CP_ASYNC16(Bb + d, Bs + (size_t)(n0 + row) * DIM + k0 + grp * 8);
        }
        CP_COMMIT();
    };

    load_chunk(0, 0);
    load_chunk(1, 1);

    float acc[2][8][4];
#pragma unroll
    for (int i = 0; i < 2; i++)
#pragma unroll
        for (int j = 0; j < 8; j++)
#pragma unroll
            for (int q = 0; q < 4; q++) acc[i][j][q] = 0.f;

    const int lrA = wm0 + (lane & 15);
    const int lrB = wn0 + (lane & 15);
    const u32 khi = (u32)((lane >> 4) << 4);

    for (int c = 0; c < 48; c++) {
        const int st = c & 1;
        CP_WAIT(1);
        __syncthreads();
        u32 Ab = base + (u32)st * 32768u;
        u32 Bb = Ab + 16384u;
#pragma unroll
        for (int kk = 0; kk < 4; kk++) {
            u32 kb = (u32)(kk * 32) + khi;
            u32 a0[4], a1[4];
            ldsm4(a0[0], a0[1], a0[2], a0[3], Ab + swz((u32)(lrA * 128) + kb));
            ldsm4(a1[0], a1[1], a1[2], a1[3], Ab + swz((u32)((lrA + 16) * 128) + kb));
            u32 b[8][2];
#pragma unroll
            for (int nn = 0; nn < 4; nn++) {
                u32 t0, t1, t2, t3;
                ldsm4(t0, t1, t2, t3, Bb + swz((u32)((lrB + nn * 16) * 128) + kb));
                b[2 * nn][0] = t0; b[2 * nn + 1][0] = t1;
                b[2 * nn][1] = t2; b[2 * nn + 1][1] = t3;
            }
#pragma unroll
            for (int ni = 0; ni < 8; ni++) {
                mma16816(acc[0][ni], a0, b[ni]);
                mma16816(acc[1][ni], a1, b[ni]);
            }
        }
        __syncthreads();
        if (c + 2 < 48) load_chunk(c + 2, st);
    }

    const int g = lane >> 2, tg = lane & 3;
#pragma unroll
    for (int ni = 0; ni < 8; ni++) {
        int n = n0 + wn0 + ni * 8 + 2 * tg;
        float b0 = bias[n], b1 = bias[n + 1];
#pragma unroll
        for (int mi = 0; mi < 2; mi++) {
#pragma unroll
            for (int half = 0; half < 2; half++) {
                int m = m0 + wm0 + mi * 16 + half * 8 + g;
                float v0 = fmaxf(acc[mi][ni][half * 2 + 0] + b0, 0.f);
                float v1 = fmaxf(acc[mi][ni][half * 2 + 1] + b1, 0.f);
                __nv_bfloat16 h0 = __float2bfloat16(v0);
                __nv_bfloat16 h1 = __float2bfloat16(v1);
                __nv_bfloat16 l0 = __float2bfloat16(v0 - __bfloat162float(h0));
                __nv_bfloat16 l1 = __float2bfloat16(v1 - __bfloat162float(h1));
                __nv_bfloat162 hp; hp.x = h0; hp.y = h1;
                __nv_bfloat162 lp; lp.x = l0; lp.y = l1;
                *(__nv_bfloat162*)(Chi + (size_t)m * DIM + n) = hp;
                *(__nv_bfloat162*)(Clo + (size_t)m * DIM + n) = lp;
            }
        }
    }
}

// ---------------------------------------------------------------------------
// Energy: p[bh,t,s] = sigmoid(5*(q.k*0.125 + eb)), split-bf16 HMMA.
// Progressive cp.async waits: MMA on segment c overlaps load of segment c+1.
// ---------------------------------------------------------------------------
#define EN_SMEM (1024 + 3 * 32768)

__device__ __forceinline__ float sigmoid5(float e) {
    return 1.f / (1.f + __expf(-5.f * e));
}

__global__ __launch_bounds__(256, 2) void energy_kernel(
    const float* __restrict__ ebias, float* __restrict__ p) {
    extern __shared__ char smraw[];
    u32 braw = smem_u32(smraw);
    u32 base = (braw + 1023) & ~1023u;

    const int tid = threadIdx.x, lane = tid & 31, wid = tid >> 5;
    const int s0 = blockIdx.x * 128, t0 = blockIdx.y * 128;
    const int bh = blockIdx.z;
    const int b = bh >> 4, h = bh & 15;
    const int wm0 = (wid >> 1) * 32, wn0 = (wid & 1) * 64;

    const __nv_bfloat16* segQ[3] = {g_q_hi, g_q_hi, g_q_lo};
    const __nv_bfloat16* segK[3] = {g_k_hi, g_k_lo, g_k_hi};

    const int r0l = tid >> 3, grp = tid & 7;

#pragma unroll
    for (int c = 0; c < 3; c++) {
        const __nv_bfloat16* Qs = segQ[c];
        const __nv_bfloat16* Ks = segK[c];
        u32 Qb = base + (u32)c * 32768u;
        u32 Kb = Qb + 16384u;
#pragma unroll
        for (int g = 0; g < 4; g++) {
            int row = r0l + g * 32;
            u32 d = swz((u32)(row * 128 + grp * 16));
            CP_ASYNC16(Qb + d, Qs + (size_t)(b * TGT + t0 + row) * DIM + h * DH + grp * 8);
            CP_ASYNC16(Kb + d, Ks + (size_t)(b * SRC + s0 + row) * DIM + h * DH + grp * 8);
        }
        CP_COMMIT();
    }

    float acc[2][8][4];
#pragma unroll
    for (int i = 0; i < 2; i++)
#pragma unroll
        for (int j = 0; j < 8; j++)
#pragma unroll
            for (int q = 0; q < 4; q++) acc[i][j][q] = 0.f;

    const int lrA = wm0 + (lane & 15);
    const int lrB = wn0 + (lane & 15);
    const u32 khi_off = (u32)((lane >> 4) << 4);

#pragma unroll
    for (int c = 0; c < 3; c++) {
        if (c == 0)      { CP_WAIT(2); }
        else if (c == 1) { CP_WAIT(1); }
        else             { CP_WAIT(0); }
        __syncthreads();
        u32 Qb = base + (u32)c * 32768u;
        u32 Kb = Qb + 16384u;
#pragma unroll
        for (int kk = 0; kk < 4; kk++) {
            u32 kb = (u32)(kk * 32) + khi_off;
            u32 a0[4], a1[4];
            ldsm4(a0[0], a0[1], a0[2], a0[3], Qb + swz((u32)(lrA * 128) + kb));
            ldsm4(a1[0], a1[1], a1[2], a1[3], Qb + swz((u32)((lrA + 16) * 128) + kb));
            u32 bb[8][2];
#pragma unroll
            for (int nn = 0; nn < 4; nn++) {
                u32 t0r, t1r, t2r, t3r;
                ldsm4(t0r, t1r, t2r, t3r, Kb + swz((u32)((lrB + nn * 16) * 128) + kb));
                bb[2 * nn][0] = t0r; bb[2 * nn + 1][0] = t1r;
                bb[2 * nn][1] = t2r; bb[2 * nn + 1][1] = t3r;
            }
#pragma unroll
            for (int ni = 0; ni < 8; ni++) {
                mma16816(acc[0][ni], a0, bb[ni]);
                mma16816(acc[1][ni], a1, bb[ni]);
            }
        }
    }

    const float eb = ebias[0];
    const int g = lane >> 2, tg = lane & 3;
#pragma unroll
    for (int ni = 0; ni < 8; ni++) {
        int s = s0 + wn0 + ni * 8 + 2 * tg;
#pragma unroll
        for (int mi = 0; mi < 2; mi++) {
#pragma unroll
            for (int half = 0; half < 2; half++) {
                int t = t0 + wm0 + mi * 16 + half * 8 + g;
                float2 o;
                o.x = sigmoid5(acc[mi][ni][half * 2 + 0] * 0.125f + eb);
                o.y = sigmoid5(acc[mi][ni][half * 2 + 1] * 0.125f + eb);
                *(float2*)(p + ((size_t)bh * TGT + t) * SRC + s) = o;
            }
        }
    }
}

// ---------------------------------------------------------------------------
// Monotonic alignment: one warp per bh, 2 t-steps per iteration.
// s=512 split into two halves of 256; each lane owns 8 elems per half.
// The two halves' local chains AND warp scans run in parallel (ILP2);
// only the seed application couples them (one broadcast shuffle).
// ---------------------------------------------------------------------------
__global__ __launch_bounds__(32) void align_kernel(
    const float* __restrict__ p, float* __restrict__ alpha) {
    const int bh = blockIdx.x;
    const int lane = threadIdx.x;
    const float* prow = p + (size_t)bh * TGT * SRC;
    float* arow = alpha + (size_t)bh * TGT * SRC;
    const int off[2] = {lane * 8, 256 + lane * 8};

    // b = previous alpha (seed: delta at s=0)
    float b[2][8];
#pragma unroll
    for (int h = 0; h < 2; h++)
#pragma unroll
        for (int i = 0; i < 8; i++) b[h][i] = 0.f;
    if (lane == 0) b[0][0] = 1.f;

    // prefetch p rows for t=0,1 (both halves): f[t][h][j]
    float4 f[2][2][2];
#pragma unroll
    for (int t = 0; t < 2; t++)
#pragma unroll
        for (int h = 0; h < 2; h++)
#pragma unroll
            for (int j = 0; j < 2; j++)
                f[t][h][j] = *(const float4*)(prow + (size_t)t * SRC + off[h] + 4 * j);

    for (int tp = 0; tp < TGT / 2; tp++) {
        // unpack: p0 = p at step 2tp, p1 = p at step 2tp+1
        float p0[2][8], p1[2][8];
#pragma unroll
        for (int h = 0; h < 2; h++)
#pragma unroll
            for (int j = 0; j < 2; j++) {
                p0[h][4 * j + 0] = f[0][h][j].x; p0[h][4 * j + 1] = f[0][h][j].y;
                p0[h][4 * j + 2] = f[0][h][j].z; p0[h][4 * j + 3] = f[0][h][j].w;
                p1[h][4 * j + 0] = f[1][h][j].x; p1[h][4 * j + 1] = f[1][h][j].y;
                p1[h][4 * j + 2] = f[1][h][j].z; p1[h][4 * j + 3] = f[1][h][j].w;
            }
        if (tp + 1 < TGT / 2) {
            const float* np = prow + (size_t)(2 * tp + 2) * SRC;
#pragma unroll
            for (int t = 0; t < 2; t++)
#pragma unroll
                for (int h = 0; h < 2; h++)
#pragma unroll
                    for (int j = 0; j < 2; j++)
                        f[t][h][j] = *(const float4*)(np + (size_t)t * SRC + off[h] + 4 * j);
        }

        // boundary a-coefficients for elem 0 of each lane-block
        float a0f[2], a1f[2];
        {
            float pA0 = __shfl_up_sync(0xffffffffu, p0[0][7], 1);
            float pB0 = __shfl_up_sync(0xffffffffu, p0[1][7], 1);
            float pL0 = __shfl_sync(0xffffffffu, p0[0][7], 31);
            float pA1 = __shfl_up_sync(0xffffffffu, p1[0][7], 1);
            float pB1 = __shfl_up_sync(0xffffffffu, p1[1][7], 1);
            float pL1 = __shfl_sync(0xffffffffu, p1[0][7], 31);
            a0f[0] = lane ? (1.f - pA0) : 0.f;
            a0f[1] = lane ? (1.f - pB0) : (1.f - pL0);
            a1f[0] = lane ? (1.f - pA1) : 0.f;
            a1f[1] = lane ? (1.f - pB1) : (1.f - pL1);
        }

        // local chains per half (zero seed): P = (c00,c10,c11), V = (x,y)
        float s00[2], s10[2], s11[2], X[2], Y[2];
        float C00[2], C10[2], C11[2], LX[2], LY[2];
#pragma unroll
        for (int i = 0; i < 8; i++) {
#pragma unroll
            for (int h = 0; h < 2; h++) {
                float at, at1;
                if (i == 0) {
                    at = a0f[h]; at1 = a1f[h];
                    s00[h] = 1.f; s10[h] = 0.f; s11[h] = 1.f; X[h] = 0.f; Y[h] = 0.f;
                } else {
                    at = 1.f - p0[h][i - 1]; at1 = 1.f - p1[h][i - 1];
                }
                X[h] = fmaf(at, X[h], b[h][i]);
                Y[h] = fmaf(at1, Y[h], p0[h][i] * X[h]);
                s00[h] = at * s00[h];
                s10[h] = fmaf(p0[h][i], s00[h], at1 * s10[h]);
                s11[h] = at1 * s11[h];
            }
        }
#pragma unroll
        for (int h = 0; h < 2; h++) {
            C00[h] = s00[h]; C10[h] = s10[h]; C11[h] = s11[h];
            LX[h] = X[h]; LY[h] = Y[h];
        }

        // two independent warp scans (ILP2)
#pragma unroll
        for (int d = 1; d < 32; d <<= 1) {
            bool use = (lane >= d);
#pragma unroll
            for (int h = 0; h < 2; h++) {
                float g00 = __shfl_up_sync(0xffffffffu, s00[h], d);
                float g10 = __shfl_up_sync(0xffffffffu, s10[h], d);
                float g11 = __shfl_up_sync(0xffffffffu, s11[h], d);
                float gX  = __shfl_up_sync(0xffffffffu, X[h], d);
                float gY  = __shfl_up_sync(0xffffffffu, Y[h], d);
                float nX  = fmaf(s00[h], gX, X[h]);
                float nY  = fmaf(s10[h], gX, fmaf(s11[h], gY, Y[h]));
                float n00 = s00[h] * g00;
                float n10 = fmaf(s10[h], g00, s11[h] * g10);
                float n11 = s11[h] * g11;
                X[h] = use ? nX : X[h];     Y[h] = use ? nY : Y[h];
                s00[h] = use ? n00 : s00[h]; s10[h] = use ? n10 : s10[h];
                s11[h] = use ? n11 : s11[h];
            }
        }

        // half-1 end state (global state after s=255), from scanA lane 31
        float H1X = __shfl_sync(0xffffffffu, X[0], 31);
        float H1Y = __shfl_sync(0xffffffffu, Y[0], 31);

        // seeds: half0 = exclusive scanA V; half1 = exclusive scanB (P,V) applied to H1
        float SX[2], SY[2];
        {
            float exX0 = __shfl_up_sync(0xffffffffu, X[0], 1);
            float exY0 = __shfl_up_sync(0xffffffffu, Y[0], 1);
            SX[0] = lane ? exX0 : 0.f;
            SY[0] = lane ? exY0 : 0.f;
            float e00 = __shfl_up_sync(0xffffffffu, s00[1], 1);
            float e10 = __shfl_up_sync(0xffffffffu, s10[1], 1);
            float e11 = __shfl_up_sync(0xffffffffu, s11[1], 1);
            float exX1 = __shfl_up_sync(0xffffffffu, X[1], 1);
            float exY1 = __shfl_up_sync(0xffffffffu, Y[1], 1);
            if (lane == 0) { e00 = 1.f; e10 = 0.f; e11 = 1.f; exX1 = 0.f; exY1 = 0.f; }
            SX[1] = fmaf(e00, H1X, exX1);
            SY[1] = fmaf(e10, H1X, fmaf(e11, H1Y, exY1));
        }

        // seed-recompute both halves (ILP2), write alpha, update b
        float o0[2][8];
#pragma unroll
        for (int i = 0; i < 8; i++) {
#pragma unroll
            for (int h = 0; h < 2; h++) {
                float at  = (i == 0) ? a0f[h] : (1.f - p0[h][i - 1]);
                float at1 = (i == 0) ? a1f[h] : (1.f - p1[h][i - 1]);
                SX[h] = fmaf(at, SX[h], b[h][i]);
                float o = p0[h][i] * SX[h];
                SY[h] = fmaf(at1, SY[h], o);
                o0[h][i] = o;
                b[h][i] = p1[h][i] * SY[h];
            }
        }
        float* a0p = arow + (size_t)(2 * tp) * SRC;
        float* a1p = a0p + SRC;
#pragma unroll
        for (int h = 0; h < 2; h++) {
#pragma unroll
            for (int j = 0; j < 2; j++) {
                *(float4*)(a0p + off[h] + 4 * j) =
                    make_float4(o0[h][4 * j], o0[h][4 * j + 1], o0[h][4 * j + 2], o0[h][4 * j + 3]);
                *(float4*)(a1p + off[h] + 4 * j) =
                    make_float4(b[h][4 * j], b[h][4 * j + 1], b[h][4 * j + 2], b[h][4 * j + 3]);
            }
        }
    }
}

// ---------------------------------------------------------------------------
extern "C" void kernel_launch(void* const* d_in, const int* in_sizes, int n_in,
                              void* d_out, int out_size) {
    const float* seqs = (const float*)d_in[0];
    const float* keys = (const float*)d_in[1];
    const float* q_w  = (const float*)d_in[2];
    const float* q_b  = (const float*)d_in[3];
    const float* k_w  = (const float*)d_in[4];
    const float* k_b  = (const float*)d_in[5];
    const float* eb   = (const float*)d_in[6];

    float* out   = (float*)d_out;
    float* p     = out;
    float* alpha = out + (size_t)NB * NH * TGT * SRC;

    cudaFuncSetAttribute(proj_kernel, cudaFuncAttributeMaxDynamicSharedMemorySize, PROJ_SMEM);
    cudaFuncSetAttribute(energy_kernel, cudaFuncAttributeMaxDynamicSharedMemorySize, EN_SMEM);

    // fused fp32 -> bf16 hi/lo splits (one launch)
    split_all_kernel<<<(N4_TOT + 255) / 256, 256>>>(seqs, keys, q_w, k_w);

    // both projections in one launch (x: 16 q-tiles + 32 k-tiles)
    proj_kernel<<<dim3(48, DIM / 128), 256, PROJ_SMEM>>>(q_b, k_b);

    // p_choose (HMMA)
    energy_kernel<<<dim3(SRC / 128, TGT / 128, NB * NH), 256, EN_SMEM>>>(eb, p);

    // alpha
    align_kernel<<<NB * NH, 32>>>(p, alpha);
}